// round 8
// baseline (speedup 1.0000x reference)
#include <cuda_runtime.h>
#include <cuda_fp16.h>
#include <cstdint>

// ---------------------------------------------------------------------------
// HypergraphAttentionLayer on GB300 (sm_103a) — single fused persistent kernel.
//   Phase 1: h ~= fp16(x) * fp16(W)  (HMMA, warp-autonomous cp.async pipeline,
//            W fragments register-resident), s1/s2 fused in epilogue.
//   grid barrier (software, all CTAs resident: grid == #SMs, 1 CTA/SM)
//   Phase 2: ea[e] = (sum_r s1*(31-r)+s2*r)/496, 16-edge MLP batches.
// ---------------------------------------------------------------------------

#define F_IN   128
#define F_OUT  64
#define DEG    32
#define NPAIRS 496.0f
#define MAX_N  200704
#define TILE_M 128
#define PITCHW 68       // 32-bit words per fp16 smem row (64 + 4 pad)
#define PITCHB 272      // bytes per fp16 smem row

__device__ float2 g_s12[MAX_N];
__device__ unsigned int g_bar;   // zero-initialized; monotonic (no reset)

// smem byte offsets
#define SM_AVEC 0                        // 512 B
#define SM_B    512                      // 64*272  = 17408 (fp16 W)
#define SM_A    (SM_B + 17408)           // 128*272 = 34816 (fp16 x)
#define SM_X0   (SM_A + 34816)           // 8 warps * 2 bufs * 8192 = 131072
#define SM_TOTAL (SM_X0 + 131072)        // 183808 B  -> 1 CTA/SM

__device__ __forceinline__ uint32_t smem_u32(const void* p) {
    uint32_t a;
    asm("{ .reg .u64 t; cvta.to.shared.u64 t, %1; cvt.u32.u64 %0, t; }"
        : "=r"(a) : "l"(p));
    return a;
}

__device__ __forceinline__ void mma_f16(float c[4],
                                        uint32_t a0, uint32_t a1,
                                        uint32_t a2, uint32_t a3,
                                        uint32_t b0, uint32_t b1)
{
    asm volatile(
        "mma.sync.aligned.m16n8k16.row.col.f32.f16.f16.f32 "
        "{%0,%1,%2,%3}, {%4,%5,%6,%7}, {%8,%9}, {%0,%1,%2,%3};"
        : "+f"(c[0]), "+f"(c[1]), "+f"(c[2]), "+f"(c[3])
        : "r"(a0), "r"(a1), "r"(a2), "r"(a3), "r"(b0), "r"(b1));
}

__device__ __forceinline__ void ldmatrix_x4(uint32_t& r0, uint32_t& r1,
                                            uint32_t& r2, uint32_t& r3,
                                            uint32_t addr)
{
    asm volatile(
        "ldmatrix.sync.aligned.m8n8.x4.shared.b16 {%0,%1,%2,%3}, [%4];"
        : "=r"(r0), "=r"(r1), "=r"(r2), "=r"(r3) : "r"(addr));
}

__device__ __forceinline__ uint2 pack_h4(float4 v) {
    __half2 p01 = __floats2half2_rn(v.x, v.y);
    __half2 p23 = __floats2half2_rn(v.z, v.w);
    uint2 pk;
    pk.x = *reinterpret_cast<uint32_t*>(&p01);
    pk.y = *reinterpret_cast<uint32_t*>(&p23);
    return pk;
}

// software grid barrier; safe: all CTAs co-resident (grid == #SMs, 1 CTA/SM).
// monotonic counter => deterministic across graph replays, no reset needed.
__device__ __forceinline__ void grid_barrier(int grid) {
    __syncthreads();
    if (threadIdx.x == 0) {
        __threadfence();
        unsigned int old = atomicAdd(&g_bar, 1u);
        unsigned int tgt = (old / (unsigned)grid + 1u) * (unsigned)grid;
        unsigned int cur;
        do {
            asm volatile("ld.acquire.gpu.u32 %0, [%1];"
                         : "=r"(cur) : "l"(&g_bar));
        } while (cur < tgt);
    }
    __syncthreads();
}

// ---------------------------------------------------------------------------
__global__ __launch_bounds__(256, 1)
void fused_kernel(const float* __restrict__ x,
                  const float* __restrict__ W,
                  const float* __restrict__ a,
                  const int* __restrict__ nodes,
                  float* __restrict__ h_out,
                  float* __restrict__ ea_out,
                  int N, int tiles, int H)
{
    extern __shared__ char smem[];
    float*    As = reinterpret_cast<float*>(smem + SM_AVEC);
    uint32_t* B  = reinterpret_cast<uint32_t*>(smem + SM_B);
    uint32_t* A  = reinterpret_cast<uint32_t*>(smem + SM_A);

    const int tid  = threadIdx.x;
    const int wid  = tid >> 5;
    const int lane = tid & 31;
    const int qr   = lane >> 2;
    const int qc   = lane & 3;
    const int g    = gridDim.x;

    // ======================= PHASE 1: GEMM =======================
    {
        const uint32_t xw_u32 = smem_u32(smem + SM_X0) + (uint32_t)wid * 16384u;

        auto issue_copy = [&](int row0, int b) {
            uint32_t base = xw_u32 + (uint32_t)b * 8192u;
            int r0 = row0 + wid * 16;
#pragma unroll
            for (int it = 0; it < 16; ++it) {
                int idx = it * 32 + lane;
                int rg  = r0 + (idx >> 5);
                if (rg >= N) rg = N - 1;
                const float4* src =
                    reinterpret_cast<const float4*>(x) + (size_t)rg * 32 + (idx & 31);
                asm volatile("cp.async.cg.shared.global [%0], [%1], 16;"
                             :: "r"(base + (uint32_t)idx * 16u), "l"(src) : "memory");
            }
            asm volatile("cp.async.commit_group;" ::: "memory");
        };

        if (blockIdx.x < tiles)     issue_copy(blockIdx.x * TILE_M, 0);
        if (blockIdx.x + g < tiles) issue_copy((blockIdx.x + g) * TILE_M, 1);

        // W -> fp16 smem (once)
#pragma unroll
        for (int it = 0; it < 8; ++it) {
            int idx = it * 256 + tid;
            int n   = idx >> 5;
            int c4  = idx & 31;
            float4 v = reinterpret_cast<const float4*>(W)[n * 32 + c4];
            *reinterpret_cast<uint2*>(B + n * PITCHW + c4 * 2) = pack_h4(v);
        }
        if (tid < 2 * F_OUT) As[tid] = a[tid];
        __syncthreads();

        // all B fragments -> registers
        uint32_t bf[8][8][2];
        {
            int rowselB  = (lane & 7) + ((lane >> 4) & 1) * 8;
            int byteselB = ((lane >> 3) & 1) * 16;
            uint32_t b_base = smem_u32(smem + SM_B) + rowselB * PITCHB + byteselB;
#pragma unroll
            for (int jp = 0; jp < 4; ++jp)
#pragma unroll
                for (int kk = 0; kk < 8; ++kk)
                    ldmatrix_x4(bf[kk][2 * jp][0], bf[kk][2 * jp][1],
                                bf[kk][2 * jp + 1][0], bf[kk][2 * jp + 1][1],
                                b_base + jp * 16 * PITCHB + kk * 32);
        }

        const int rowselA  = (lane & 7) + ((lane >> 3) & 1) * 8;
        const int byteselA = ((lane >> 4) & 1) * 16;
        const uint32_t a_base = smem_u32(smem + SM_A) +
            (wid * 16 + rowselA) * PITCHB + byteselA;

        int buf = 0;
        for (int t = blockIdx.x; t < tiles; t += g, buf ^= 1) {
            const int row0 = t * TILE_M;

            if (t + g < tiles)
                asm volatile("cp.async.wait_group 1;" ::: "memory");
            else
                asm volatile("cp.async.wait_group 0;" ::: "memory");

            const float4* Xb = reinterpret_cast<const float4*>(
                smem + SM_X0 + wid * 16384 + buf * 8192);
            uint32_t* Aw = A + wid * 16 * PITCHW;
#pragma unroll
            for (int it = 0; it < 16; ++it) {
                int idx = it * 32 + lane;
                *reinterpret_cast<uint2*>(
                    Aw + (idx >> 5) * PITCHW + (idx & 31) * 2) = pack_h4(Xb[idx]);
            }
            __syncwarp();

            if (t + 2 * g < tiles) issue_copy((t + 2 * g) * TILE_M, buf);

            float c[8][4];
#pragma unroll
            for (int j = 0; j < 8; ++j)
#pragma unroll
                for (int q = 0; q < 4; ++q) c[j][q] = 0.f;

#pragma unroll
            for (int kk = 0; kk < 8; ++kk) {
                uint32_t a0, a1, a2, a3;
                ldmatrix_x4(a0, a1, a2, a3, a_base + kk * 32);
#pragma unroll
                for (int j = 0; j < 8; ++j)
                    mma_f16(c[j], a0, a1, a2, a3, bf[kk][j][0], bf[kk][j][1]);
            }

            // epilogue
            float s1a = 0.f, s2a = 0.f, s1b = 0.f, s2b = 0.f;
            int ra = row0 + wid * 16 + qr;
            int rb = ra + 8;
#pragma unroll
            for (int j = 0; j < 8; ++j) {
                int n = j * 8 + qc * 2;
                float a1v = As[n],         a2v = As[n + 1];
                float b1v = As[F_OUT + n], b2v = As[F_OUT + n + 1];
                float* cc = c[j];
                if (ra < N)
                    *reinterpret_cast<float2*>(h_out + (size_t)ra * F_OUT + n) =
                        make_float2(cc[0], cc[1]);
                if (rb < N)
                    *reinterpret_cast<float2*>(h_out + (size_t)rb * F_OUT + n) =
                        make_float2(cc[2], cc[3]);
                s1a = fmaf(cc[0], a1v, fmaf(cc[1], a2v, s1a));
                s2a = fmaf(cc[0], b1v, fmaf(cc[1], b2v, s2a));
                s1b = fmaf(cc[2], a1v, fmaf(cc[3], a2v, s1b));
                s2b = fmaf(cc[2], b1v, fmaf(cc[3], b2v, s2b));
            }
#pragma unroll
            for (int off = 1; off <= 2; off <<= 1) {
                s1a += __shfl_xor_sync(0xFFFFFFFFu, s1a, off);
                s2a += __shfl_xor_sync(0xFFFFFFFFu, s2a, off);
                s1b += __shfl_xor_sync(0xFFFFFFFFu, s1b, off);
                s2b += __shfl_xor_sync(0xFFFFFFFFu, s2b, off);
            }
            if (qc == 0) {
                if (ra < N) g_s12[ra] = make_float2(s1a, s2a);
                if (rb < N) g_s12[rb] = make_float2(s1b, s2b);
            }
        }
    }

    // ======================= grid barrier =======================
    grid_barrier(g);

    // ======================= PHASE 2: edges =======================
    {
        const int nw    = g * 8;
        const int gwarp = blockIdx.x * 8 + wid;
        int start = (int)(((long long)gwarp * H) / nw);
        int end   = (int)(((long long)(gwarp + 1) * H) / nw);

        const int r0  = (lane & 7) * 4;
        const float fl = (float)(31 - r0), fr = (float)r0;
        const int sub = lane >> 3;

        int e0 = start;
        // 16-edge batches: 4 int4 index loads + 16 gathers per lane (MLP 16)
        for (; e0 + 16 <= end; e0 += 16) {
            const int4* base =
                reinterpret_cast<const int4*>(nodes + (size_t)e0 * DEG);
            int4 nd[4];
#pragma unroll
            for (int k = 0; k < 4; ++k) nd[k] = base[k * 32 + lane];

            float v[4];
#pragma unroll
            for (int k = 0; k < 4; ++k) {
                float2 s0 = g_s12[nd[k].x];
                float2 s1 = g_s12[nd[k].y];
                float2 s2 = g_s12[nd[k].z];
                float2 s3 = g_s12[nd[k].w];
                v[k] = s0.x * fl         + s0.y * fr
                     + s1.x * (fl - 1.f) + s1.y * (fr + 1.f)
                     + s2.x * (fl - 2.f) + s2.y * (fr + 2.f)
                     + s3.x * (fl - 3.f) + s3.y * (fr + 3.f);
            }
#pragma unroll
            for (int off = 1; off <= 4; off <<= 1)
#pragma unroll
                for (int k = 0; k < 4; ++k)
                    v[k] += __shfl_xor_sync(0xFFFFFFFFu, v[k], off);

            if ((lane & 7) == 0) {
#pragma unroll
                for (int k = 0; k < 4; ++k)
                    ea_out[e0 + 4 * k + sub] = v[k] * (1.0f / NPAIRS);
            }
        }
        // 8-edge batch
        for (; e0 + 8 <= end; e0 += 8) {
            const int4* base =
                reinterpret_cast<const int4*>(nodes + (size_t)e0 * DEG);
            int4 n0 = base[lane];
            int4 n1 = base[32 + lane];
            float2 s00 = g_s12[n0.x], s01 = g_s12[n0.y];
            float2 s02 = g_s12[n0.z], s03 = g_s12[n0.w];
            float2 s10 = g_s12[n1.x], s11 = g_s12[n1.y];
            float2 s12v = g_s12[n1.z], s13 = g_s12[n1.w];

            float v0 = s00.x * fl         + s00.y * fr
                     + s01.x * (fl - 1.f) + s01.y * (fr + 1.f)
                     + s02.x * (fl - 2.f) + s02.y * (fr + 2.f)
                     + s03.x * (fl - 3.f) + s03.y * (fr + 3.f);
            float v1 = s10.x * fl         + s10.y * fr
                     + s11.x * (fl - 1.f) + s11.y * (fr + 1.f)
                     + s12v.x * (fl - 2.f) + s12v.y * (fr + 2.f)
                     + s13.x * (fl - 3.f) + s13.y * (fr + 3.f);
#pragma unroll
            for (int off = 1; off <= 4; off <<= 1) {
                v0 += __shfl_xor_sync(0xFFFFFFFFu, v0, off);
                v1 += __shfl_xor_sync(0xFFFFFFFFu, v1, off);
            }
            if ((lane & 7) == 0) {
                ea_out[e0 + sub]     = v0 * (1.0f / NPAIRS);
                ea_out[e0 + 4 + sub] = v1 * (1.0f / NPAIRS);
            }
        }
        // per-edge tail
        for (; e0 < end; ++e0) {
            int node = nodes[(size_t)e0 * DEG + lane];
            float2 s = g_s12[node];
            float v = s.x * (float)(DEG - 1 - lane) + s.y * (float)lane;
#pragma unroll
            for (int off = 16; off > 0; off >>= 1)
                v += __shfl_xor_sync(0xFFFFFFFFu, v, off);
            if (lane == 0) ea_out[e0] = v * (1.0f / NPAIRS);
        }
    }
}

// ---------------------------------------------------------------------------
extern "C" void kernel_launch(void* const* d_in, const int* in_sizes, int n_in,
                              void* d_out, int out_size)
{
    const float* x    = (const float*)d_in[0];
    const float* W    = (const float*)d_in[1];
    const float* a    = (const float*)d_in[2];
    const int*   hidx = (const int*)d_in[3];

    int N = in_sizes[0] / F_IN;    // 200000
    int E = in_sizes[3] / 2;       // 1,600,000
    int H = E / DEG;               // 50000

    float* h_out  = (float*)d_out;
    float* ea_out = (float*)d_out + (size_t)N * F_OUT;
    const int* nodes = hidx;

    int sms = 0;
    cudaDeviceGetAttribute(&sms, cudaDevAttrMultiProcessorCount, 0);
    if (sms <= 0) sms = 148;

    cudaFuncSetAttribute(fused_kernel,
                         cudaFuncAttributeMaxDynamicSharedMemorySize, SM_TOTAL);

    int tiles = (N + TILE_M - 1) / TILE_M;    // 1563
    fused_kernel<<<sms, 256, SM_TOTAL>>>(x, W, a, nodes, h_out, ea_out,
                                         N, tiles, H);
}

// round 9
// speedup vs baseline: 1.0840x; 1.0840x over previous
#include <cuda_runtime.h>
#include <cuda_fp16.h>
#include <cstdint>

// ---------------------------------------------------------------------------
// HypergraphAttentionLayer on GB300 (sm_103a), portable-PTX tensor path.
//   h ~= fp16(x) * fp16(W)   (1-chain fp16 HMMA)
//   s1/s2 fused in epilogue; ea[e] = (sum_r s1*(31-r)+s2*r)/496
// Persistent warp-autonomous GEMM; W frags register-resident; h epilogue
// staged through smem for fully-coalesced STG.128 (line-granular wavefronts).
// ---------------------------------------------------------------------------

#define F_IN   128
#define F_OUT  64
#define DEG    32
#define NPAIRS 496.0f
#define MAX_N  200704
#define TILE_M 128
#define PITCHW 68       // 32-bit words per fp16 smem row (64 + 4 pad)
#define PITCHB 272      // bytes per fp16 smem row
#define HPITCH 68       // fp32 words per h-staging row (64 + 4 pad)

__device__ float2 g_s12[MAX_N];

// smem byte offsets
#define SM_AVEC 0                        // 512 B
#define SM_B    512                      // 64*272  = 17408 (fp16 W)
#define SM_A    (SM_B + 17408)           // 128*272 = 34816 (fp16 x)
#define SM_HST  (SM_A + 34816)           // 8 warps * 16*68*4 = 34816 (h stage)
#define SM_X0   (SM_HST + 34816)         // 8 warps * 2 bufs * 8192 = 131072
#define SM_TOTAL (SM_X0 + 131072)        // 218624 B -> 1 CTA/SM

__device__ __forceinline__ uint32_t smem_u32(const void* p) {
    uint32_t a;
    asm("{ .reg .u64 t; cvta.to.shared.u64 t, %1; cvt.u32.u64 %0, t; }"
        : "=r"(a) : "l"(p));
    return a;
}

__device__ __forceinline__ void mma_f16(float c[4],
                                        uint32_t a0, uint32_t a1,
                                        uint32_t a2, uint32_t a3,
                                        uint32_t b0, uint32_t b1)
{
    asm volatile(
        "mma.sync.aligned.m16n8k16.row.col.f32.f16.f16.f32 "
        "{%0,%1,%2,%3}, {%4,%5,%6,%7}, {%8,%9}, {%0,%1,%2,%3};"
        : "+f"(c[0]), "+f"(c[1]), "+f"(c[2]), "+f"(c[3])
        : "r"(a0), "r"(a1), "r"(a2), "r"(a3), "r"(b0), "r"(b1));
}

__device__ __forceinline__ void ldmatrix_x4(uint32_t& r0, uint32_t& r1,
                                            uint32_t& r2, uint32_t& r3,
                                            uint32_t addr)
{
    asm volatile(
        "ldmatrix.sync.aligned.m8n8.x4.shared.b16 {%0,%1,%2,%3}, [%4];"
        : "=r"(r0), "=r"(r1), "=r"(r2), "=r"(r3) : "r"(addr));
}

__device__ __forceinline__ uint2 pack_h4(float4 v) {
    __half2 p01 = __floats2half2_rn(v.x, v.y);
    __half2 p23 = __floats2half2_rn(v.z, v.w);
    uint2 pk;
    pk.x = *reinterpret_cast<uint32_t*>(&p01);
    pk.y = *reinterpret_cast<uint32_t*>(&p23);
    return pk;
}

// ---------------------------------------------------------------------------
// Persistent GEMM: grid = #SMs, 256 threads (8 warps). Warp w owns rows
// [t*128 + w*16, +16); self-pipelined cp.async; B frags in registers.
// ---------------------------------------------------------------------------
__global__ __launch_bounds__(256, 1)
void gemm_persist_kernel(const float* __restrict__ x,
                         const float* __restrict__ W,
                         const float* __restrict__ a,
                         float* __restrict__ h_out,
                         int N, int tiles)
{
    extern __shared__ char smem[];
    float*    As = reinterpret_cast<float*>(smem + SM_AVEC);
    uint32_t* B  = reinterpret_cast<uint32_t*>(smem + SM_B);
    uint32_t* A  = reinterpret_cast<uint32_t*>(smem + SM_A);

    const int tid  = threadIdx.x;
    const int wid  = tid >> 5;
    const int lane = tid & 31;
    const int qr   = lane >> 2;
    const int qc   = lane & 3;
    const int g    = gridDim.x;

    float* Hs = reinterpret_cast<float*>(smem + SM_HST) + wid * 16 * HPITCH;
    const uint32_t xw_u32 = smem_u32(smem + SM_X0) + (uint32_t)wid * 16384u;

    auto issue_copy = [&](int row0, int b) {
        uint32_t base = xw_u32 + (uint32_t)b * 8192u;
        int r0 = row0 + wid * 16;
#pragma unroll
        for (int it = 0; it < 16; ++it) {
            int idx = it * 32 + lane;
            int rg  = r0 + (idx >> 5);
            if (rg >= N) rg = N - 1;
            const float4* src =
                reinterpret_cast<const float4*>(x) + (size_t)rg * 32 + (idx & 31);
            asm volatile("cp.async.cg.shared.global [%0], [%1], 16;"
                         :: "r"(base + (uint32_t)idx * 16u), "l"(src) : "memory");
        }
        asm volatile("cp.async.commit_group;" ::: "memory");
    };

    if (blockIdx.x < tiles)     issue_copy(blockIdx.x * TILE_M, 0);
    if (blockIdx.x + g < tiles) issue_copy((blockIdx.x + g) * TILE_M, 1);

    // ---- W (64x128 fp32) -> fp16 smem, once per CTA ----
#pragma unroll
    for (int it = 0; it < 8; ++it) {
        int idx = it * 256 + tid;
        int n   = idx >> 5;
        int c4  = idx & 31;
        float4 v = reinterpret_cast<const float4*>(W)[n * 32 + c4];
        *reinterpret_cast<uint2*>(B + n * PITCHW + c4 * 2) = pack_h4(v);
    }
    if (tid < 2 * F_OUT) As[tid] = a[tid];
    __syncthreads();

    // ---- all B fragments -> registers (held for whole kernel) ----
    uint32_t bf[8][8][2];
    {
        int rowselB  = (lane & 7) + ((lane >> 4) & 1) * 8;
        int byteselB = ((lane >> 3) & 1) * 16;
        uint32_t b_base = smem_u32(smem + SM_B) + rowselB * PITCHB + byteselB;
#pragma unroll
        for (int jp = 0; jp < 4; ++jp)
#pragma unroll
            for (int kk = 0; kk < 8; ++kk)
                ldmatrix_x4(bf[kk][2 * jp][0], bf[kk][2 * jp][1],
                            bf[kk][2 * jp + 1][0], bf[kk][2 * jp + 1][1],
                            b_base + jp * 16 * PITCHB + kk * 32);
    }

    const int rowselA  = (lane & 7) + ((lane >> 3) & 1) * 8;
    const int byteselA = ((lane >> 4) & 1) * 16;
    const uint32_t a_base = smem_u32(smem + SM_A) +
        (wid * 16 + rowselA) * PITCHB + byteselA;

    // ---- warp-autonomous persistent loop ----
    int buf = 0;
    for (int t = blockIdx.x; t < tiles; t += g, buf ^= 1) {
        const int row0 = t * TILE_M;

        if (t + g < tiles)
            asm volatile("cp.async.wait_group 1;" ::: "memory");
        else
            asm volatile("cp.async.wait_group 0;" ::: "memory");

        // convert my Xraw[buf] -> my A slice
        const float4* Xb = reinterpret_cast<const float4*>(
            smem + SM_X0 + wid * 16384 + buf * 8192);
        uint32_t* Aw = A + wid * 16 * PITCHW;
#pragma unroll
        for (int it = 0; it < 16; ++it) {
            int idx = it * 32 + lane;
            *reinterpret_cast<uint2*>(
                Aw + (idx >> 5) * PITCHW + (idx & 31) * 2) = pack_h4(Xb[idx]);
        }
        __syncwarp();

        if (t + 2 * g < tiles) issue_copy((t + 2 * g) * TILE_M, buf);

        // ---- MMA: ldmatrix A frags, B frags from registers ----
        float c[8][4];
#pragma unroll
        for (int j = 0; j < 8; ++j)
#pragma unroll
            for (int q = 0; q < 4; ++q) c[j][q] = 0.f;

#pragma unroll
        for (int kk = 0; kk < 8; ++kk) {
            uint32_t a0, a1, a2, a3;
            ldmatrix_x4(a0, a1, a2, a3, a_base + kk * 32);
#pragma unroll
            for (int j = 0; j < 8; ++j)
                mma_f16(c[j], a0, a1, a2, a3, bf[kk][j][0], bf[kk][j][1]);
        }

        // ---- epilogue: fold s1/s2 + stage h in smem, coalesced STG.128 ----
        {
            float s1a = 0.f, s2a = 0.f, s1b = 0.f, s2b = 0.f;
#pragma unroll
            for (int j = 0; j < 8; ++j) {
                int n = j * 8 + qc * 2;
                float a1v = As[n],         a2v = As[n + 1];
                float b1v = As[F_OUT + n], b2v = As[F_OUT + n + 1];
                float* cc = c[j];
                // stage into padded smem (rows qr, qr+8 of this warp's tile)
                *reinterpret_cast<float2*>(Hs + qr * HPITCH + n) =
                    make_float2(cc[0], cc[1]);
                *reinterpret_cast<float2*>(Hs + (qr + 8) * HPITCH + n) =
                    make_float2(cc[2], cc[3]);
                s1a = fmaf(cc[0], a1v, fmaf(cc[1], a2v, s1a));
                s2a = fmaf(cc[0], b1v, fmaf(cc[1], b2v, s2a));
                s1b = fmaf(cc[2], a1v, fmaf(cc[3], a2v, s1b));
                s2b = fmaf(cc[2], b1v, fmaf(cc[3], b2v, s2b));
            }
#pragma unroll
            for (int off = 1; off <= 2; off <<= 1) {
                s1a += __shfl_xor_sync(0xFFFFFFFFu, s1a, off);
                s2a += __shfl_xor_sync(0xFFFFFFFFu, s2a, off);
                s1b += __shfl_xor_sync(0xFFFFFFFFu, s1b, off);
                s2b += __shfl_xor_sync(0xFFFFFFFFu, s2b, off);
            }
            int ra = row0 + wid * 16 + qr;
            int rb = ra + 8;
            if (qc == 0) {
                if (ra < N) g_s12[ra] = make_float2(s1a, s2a);
                if (rb < N) g_s12[rb] = make_float2(s1b, s2b);
            }
            __syncwarp();

            // coalesced copy: this warp's 16 rows are contiguous in h_out
            int rowbase = row0 + wid * 16;
            if (rowbase + 16 <= N) {
                float4* dst = reinterpret_cast<float4*>(
                    h_out + (size_t)rowbase * F_OUT);
#pragma unroll
                for (int i = 0; i < 8; ++i) {
                    int idx = i * 32 + lane;       // float4 idx 0..255
                    int r   = idx >> 4;            // 16 float4 per row
                    int cw  = (idx & 15) * 4;
                    dst[idx] = *reinterpret_cast<float4*>(Hs + r * HPITCH + cw);
                }
            } else {
#pragma unroll
                for (int i = 0; i < 8; ++i) {
                    int idx = i * 32 + lane;
                    int r   = idx >> 4;
                    int cw  = (idx & 15) * 4;
                    if (rowbase + r < N)
                        reinterpret_cast<float4*>(
                            h_out + (size_t)(rowbase + r) * F_OUT)[idx & 15] =
                            *reinterpret_cast<float4*>(Hs + r * HPITCH + cw);
                }
            }
            __syncwarp();
        }
    }
}

// ---------------------------------------------------------------------------
// Edge attention: one warp = 8 edges (proven 10.6us shape).
// ---------------------------------------------------------------------------
__global__ __launch_bounds__(256)
void edge_attn_kernel(const int* __restrict__ nodes,
                      float* __restrict__ ea_out,
                      int H)
{
    int gw   = (blockIdx.x * 256 + threadIdx.x) >> 5;
    int lane = threadIdx.x & 31;
    int e0   = gw * 8;
    if (e0 >= H) return;

    if (e0 + 8 <= H) {
        const int4* base = reinterpret_cast<const int4*>(nodes + (size_t)e0 * DEG);
        int4 n0 = base[lane];
        int4 n1 = base[32 + lane];
        int r0 = (lane & 7) * 4;

        float2 s00 = g_s12[n0.x], s01 = g_s12[n0.y];
        float2 s02 = g_s12[n0.z], s03 = g_s12[n0.w];
        float2 s10 = g_s12[n1.x], s11 = g_s12[n1.y];
        float2 s12v = g_s12[n1.z], s13 = g_s12[n1.w];

        float fl = (float)(31 - r0), fr = (float)r0;
        float v0 = s00.x * fl         + s00.y * fr
                 + s01.x * (fl - 1.f) + s01.y * (fr + 1.f)
                 + s02.x * (fl - 2.f) + s02.y * (fr + 2.f)
                 + s03.x * (fl - 3.f) + s03.y * (fr + 3.f);
        float v1 = s10.x * fl         + s10.y * fr
                 + s11.x * (fl - 1.f) + s11.y * (fr + 1.f)
                 + s12v.x * (fl - 2.f) + s12v.y * (fr + 2.f)
                 + s13.x * (fl - 3.f) + s13.y * (fr + 3.f);

#pragma unroll
        for (int off = 1; off <= 4; off <<= 1) {
            v0 += __shfl_xor_sync(0xFFFFFFFFu, v0, off);
            v1 += __shfl_xor_sync(0xFFFFFFFFu, v1, off);
        }
        if ((lane & 7) == 0) {
            int eg = e0 + (lane >> 3);
            ea_out[eg]     = v0 * (1.0f / NPAIRS);
            ea_out[eg + 4] = v1 * (1.0f / NPAIRS);
        }
    } else {
        for (int i = 0; i < 8; ++i) {
            int e = e0 + i;
            if (e >= H) break;
            int node = nodes[(size_t)e * DEG + lane];
            float2 s = g_s12[node];
            float v = s.x * (float)(DEG - 1 - lane) + s.y * (float)lane;
#pragma unroll
            for (int off = 16; off > 0; off >>= 1)
                v += __shfl_xor_sync(0xFFFFFFFFu, v, off);
            if (lane == 0) ea_out[e] = v * (1.0f / NPAIRS);
        }
    }
}

// ---------------------------------------------------------------------------
extern "C" void kernel_launch(void* const* d_in, const int* in_sizes, int n_in,
                              void* d_out, int out_size)
{
    const float* x    = (const float*)d_in[0];
    const float* W    = (const float*)d_in[1];
    const float* a    = (const float*)d_in[2];
    const int*   hidx = (const int*)d_in[3];

    int N = in_sizes[0] / F_IN;    // 200000
    int E = in_sizes[3] / 2;       // 1,600,000
    int H = E / DEG;               // 50000

    float* h_out  = (float*)d_out;
    float* ea_out = (float*)d_out + (size_t)N * F_OUT;
    const int* nodes = hidx;

    int sms = 0;
    cudaDeviceGetAttribute(&sms, cudaDevAttrMultiProcessorCount, 0);
    if (sms <= 0) sms = 148;

    cudaFuncSetAttribute(gemm_persist_kernel,
                         cudaFuncAttributeMaxDynamicSharedMemorySize, SM_TOTAL);

    int tiles = (N + TILE_M - 1) / TILE_M;    // 1563
    gemm_persist_kernel<<<sms, 256, SM_TOTAL>>>(x, W, a, h_out, N, tiles);

    {
        int warps  = (H + 7) / 8;             // 6250
        int blocks = (warps * 32 + 255) / 256;
        edge_attn_kernel<<<blocks, 256>>>(nodes, ea_out, H);
    }
}